// round 6
// baseline (speedup 1.0000x reference)
#include <cuda_runtime.h>
#include <math.h>

#define SR          44100.0
#define N_SAMPLES   131072
#define N_GRAINS    512
#define GRAIN_N     4096
#define BATCH       32
#define LOG2_F0_MIN 8.0f      /* log2(256) */
#define LOG2_F0_MAX 13.0f     /* log2(8192) */
#define TYP_SLOPE   14.35546875f  /* 44100/(12*256) */
#define PI_F        3.14159265358979323846f
#define TWO_PI_F    6.28318530717958647692f
#define TWO_PI_D    6.283185307179586476925286766559

// ---- scratch (no allocations allowed) ----
__device__ double g_Sc[BATCH * 128];         // S[32k] per batch (chunk seeds)
__device__ double g_Dd[BATCH * 128];         // pref*exp(a*(32k+1)) (delta seeds)
__device__ float  g_rho[BATCH];              // exp(a): per-sample freq ratio
__device__ double g_f0s[BATCH * N_GRAINS];   // f0/SR per grain
__device__ float  g_coeff[BATCH * N_GRAINS]; // amp_norm / sqrt(f0)
__device__ float  g_window[GRAIN_N];         // sin^2(pi t / GRAIN_N)
__device__ double g_sum[BATCH];              // ||x||^2 accumulator

// ============================================================
// Kernel 1: per-batch prep. 32 blocks x 512 threads.
//  Closed form of the reference cumsum (grain part factored out):
//   S[t] = pref*expm1(a(t+1))/denom,  a=gamma*ln2/SR, pref=e^{-2048a},
//   denom=expm1(a).  Increment: S[t+1]-S[t] = pref*exp(a(t+1)).
// ============================================================
__global__ void prep_kernel(const float* __restrict__ theta_d,
                            const float* __restrict__ theta_s,
                            const float* __restrict__ log2_f0_u) {
    const int b   = blockIdx.x;
    const int tid = threadIdx.x;

    const float d     = theta_d[b];
    const float slope = theta_s[b] * 2.0f - 1.0f;

    // gamma in fp32 to track the reference's fp32 value
    const float gamma_f = tanf(0.95f * slope * (PI_F * 0.5f)) * TYP_SLOPE * 0.25f;
    const double a = (double)gamma_f * 0.6931471805599453 / SR;

    if (tid < 128) {
        const int k = tid;
        if (a == 0.0) {
            g_Sc[b * 128 + k] = (double)(32 * k + 1);
            g_Dd[b * 128 + k] = 1.0;
        } else {
            const double pref  = exp(-2048.0 * a);
            const double denom = expm1(a);
            g_Sc[b * 128 + k] = pref * expm1(a * (double)(32 * k + 1)) / denom;
            g_Dd[b * 128 + k] = pref * exp(a * (double)(32 * k + 1));
        }
    }
    if (tid == 0) {
        g_rho[b] = (float)exp(a);
        g_sum[b] = 0.0;   // re-zero every replay
    }

    // ---- per-grain quantities ----
    const float offset = 0.25f * d + 0.75f * d * d;
    const float so0  = (1.0f - d) * (float)N_GRAINS * (0.0f - offset);
    const float amp0 = 1.0f / (1.0f + expf(2.0f * so0));   // max amp (g=0)

    for (int g = tid; g < N_GRAINS; g += blockDim.x) {
        const int idx = b * N_GRAINS + g;
        const float u  = log2_f0_u[idx];
        const float f0 = exp2f(u * (LOG2_F0_MAX - LOG2_F0_MIN) + LOG2_F0_MIN);
        const float so = (1.0f - d) * (float)N_GRAINS * ((float)g / (float)N_GRAINS - offset);
        const float amp = 1.0f / (1.0f + expf(2.0f * so));
        g_coeff[idx] = (amp / amp0) / sqrtf(f0);
        g_f0s[idx]   = (double)f0 / SR;
    }

    if (b == 0) {
        for (int t = tid; t < GRAIN_N; t += blockDim.x) {
            const float w = sinpif((float)t / (float)GRAIN_N);
            g_window[t] = w * w;
        }
    }
}

// ============================================================
// Kernel 2: synth. grid (512, 32), 128 threads; one block per grain.
// Thread t owns contiguous samples [32t, 32t+32): fp64 seed once,
// then pure-fp32 phase walk (delta < 1 cycle, ratio rho per step).
// Staged via padded smem (conflict-free both directions), flushed
// with coalesced REDs. Window/coeff applied at flush.
// ============================================================
__global__ void __launch_bounds__(128)
synth_kernel(const int* __restrict__ onsets, float* __restrict__ out) {
    __shared__ float sbuf[32 * 129];   // sbuf[129*n + t] = sin for sample 32t+n

    const int g = blockIdx.x;
    const int b = blockIdx.y;
    const int idx = b * N_GRAINS + g;
    const int t   = threadIdx.x;

    const double f0s = g_f0s[idx];

    // fp64 seed for this chunk
    const double P0 = f0s * g_Sc[b * 128 + t];
    const double fr = P0 - rint(P0);                       // [-0.5, 0.5] cycles
    float w   = (float)(fr * TWO_PI_D);                    // radians, [-pi, pi]
    float dlt = (float)(f0s * g_Dd[b * 128 + t] * TWO_PI_D); // rad/sample, < 2*pi
    const float rho = g_rho[b];

    float* __restrict__ sp = &sbuf[t];
    #pragma unroll
    for (int n = 0; n < 32; n++) {
        sp[129 * n] = __sinf(w);
        w += dlt;
        if (w >= PI_F) w -= TWO_PI_F;
        dlt *= rho;
    }
    __syncthreads();

    const int   onset = onsets[idx];
    const float coeff = g_coeff[idx];
    float* __restrict__ row = out + (size_t)b * N_SAMPLES + onset;

    #pragma unroll
    for (int i = 0; i < 32; i++) {
        const int s = 128 * i + t;                      // sample within grain
        const float v = sbuf[129 * (t & 31) + 4 * i + (t >> 5)];
        atomicAdd(row + s, v * coeff * g_window[s]);    // coalesced RED
    }
}

// ============================================================
// Kernel 3: norm^2. 2048 blocks (64/batch) x 256 threads, float4.
// ============================================================
__global__ void __launch_bounds__(256)
norm_kernel(const float4* __restrict__ out4) {
    const int b     = blockIdx.x >> 6;
    const int slice = blockIdx.x & 63;
    const int tid   = threadIdx.x;
    const float4* __restrict__ base = out4 + (size_t)b * 32768 + slice * 512;

    float s = 0.0f;
    #pragma unroll
    for (int k = 0; k < 2; k++) {
        const float4 v = base[tid + 256 * k];
        s += v.x * v.x + v.y * v.y + v.z * v.z + v.w * v.w;
    }
    __shared__ float sh[8];
    for (int off = 16; off > 0; off >>= 1)
        s += __shfl_down_sync(0xFFFFFFFFu, s, off);
    if ((tid & 31) == 0) sh[tid >> 5] = s;
    __syncthreads();
    if (tid < 8) {
        s = sh[tid];
        for (int off = 4; off > 0; off >>= 1)
            s += __shfl_down_sync(0xFFu, s, off);
        if (tid == 0) atomicAdd(&g_sum[b], (double)s);
    }
}

// ============================================================
// Kernel 4: scale by 1/norm. 1024 blocks x 256 threads, 4 float4 each.
// Each block stays within one batch (8192 float4 per batch-quarter).
// ============================================================
__global__ void __launch_bounds__(256)
scale_kernel(float4* __restrict__ out4) {
    const int b    = blockIdx.x >> 5;               // 32 blocks per batch
    const int base = blockIdx.x * 1024 + threadIdx.x;

    __shared__ float sinv;
    if (threadIdx.x == 0) sinv = (float)(1.0 / sqrt(g_sum[b]));
    __syncthreads();
    const float inv = sinv;

    #pragma unroll
    for (int k = 0; k < 4; k++) {
        float4 v = out4[base + 256 * k];
        v.x *= inv; v.y *= inv; v.z *= inv; v.w *= inv;
        out4[base + 256 * k] = v;
    }
}

extern "C" void kernel_launch(void* const* d_in, const int* in_sizes, int n_in,
                              void* d_out, int out_size) {
    const float* theta_d = (const float*)d_in[0];
    const float* theta_s = (const float*)d_in[1];
    const float* u       = (const float*)d_in[2];
    const int*   onsets  = (const int*)d_in[3];
    float* out = (float*)d_out;

    cudaMemsetAsync(out, 0, (size_t)BATCH * N_SAMPLES * sizeof(float));

    prep_kernel<<<BATCH, 512>>>(theta_d, theta_s, u);

    dim3 grid(N_GRAINS, BATCH);
    synth_kernel<<<grid, 128>>>(onsets, out);

    norm_kernel<<<2048, 256>>>((const float4*)out);

    scale_kernel<<<1024, 256>>>((float4*)out);
}

// round 9
// speedup vs baseline: 1.0118x; 1.0118x over previous
#include <cuda_runtime.h>
#include <math.h>

#define SR          44100.0
#define N_SAMPLES   131072
#define N_GRAINS    512
#define GRAIN_N     4096
#define BATCH       32
#define LOG2_F0_MIN 8.0f      /* log2(256) */
#define LOG2_F0_MAX 13.0f     /* log2(8192) */
#define TYP_SLOPE   14.35546875f  /* 44100/(12*256) */
#define PI_F        3.14159265358979323846f
#define TWO_PI_F    6.28318530717958647692f
#define TWO_PI_D    6.283185307179586476925286766559

// ---- scratch (no allocations allowed) ----
__device__ double g_Sc[BATCH * 128];         // S[32k] per batch (chunk phase seeds)
__device__ double g_Dd[BATCH * 128];         // pref*exp(a*(32k+1)) (chunk delta seeds)
__device__ float  g_rho[BATCH];              // exp(a): per-sample freq ratio
__device__ double g_f0s[BATCH * N_GRAINS];   // f0/SR per grain
__device__ float  g_coeff[BATCH * N_GRAINS]; // amp_norm / sqrt(f0)
__device__ float  g_window[GRAIN_N];         // sin^2(pi t / GRAIN_N)
__device__ double g_sum[BATCH];              // ||x||^2 accumulator

// ============================================================
// Kernel 1: per-batch prep. 32 blocks x 512 threads.
//  Closed form of the reference cumsum (grain part factored out):
//   S[t] = pref*expm1(a(t+1))/denom,  a=gamma*ln2/SR, pref=e^{-2048a},
//   denom=expm1(a).  Increment: S[t+1]-S[t] = pref*exp(a(t+1)).
// ============================================================
__global__ void prep_kernel(const float* __restrict__ theta_d,
                            const float* __restrict__ theta_s,
                            const float* __restrict__ log2_f0_u) {
    const int b   = blockIdx.x;
    const int tid = threadIdx.x;

    const float d     = theta_d[b];
    const float slope = theta_s[b] * 2.0f - 1.0f;

    // gamma in fp32 to track the reference's fp32 value
    const float gamma_f = tanf(0.95f * slope * (PI_F * 0.5f)) * TYP_SLOPE * 0.25f;
    const double a = (double)gamma_f * 0.6931471805599453 / SR;

    if (tid < 128) {
        const int k = tid;
        if (a == 0.0) {
            g_Sc[b * 128 + k] = (double)(32 * k + 1);
            g_Dd[b * 128 + k] = 1.0;
        } else {
            const double pref  = exp(-2048.0 * a);
            const double denom = expm1(a);
            g_Sc[b * 128 + k] = pref * expm1(a * (double)(32 * k + 1)) / denom;
            g_Dd[b * 128 + k] = pref * exp(a * (double)(32 * k + 1));
        }
    }
    if (tid == 0) {
        g_rho[b] = (float)exp(a);
        g_sum[b] = 0.0;   // re-zero every replay
    }

    // ---- per-grain quantities ----
    const float offset = 0.25f * d + 0.75f * d * d;
    const float so0  = (1.0f - d) * (float)N_GRAINS * (0.0f - offset);
    const float amp0 = 1.0f / (1.0f + expf(2.0f * so0));   // max amp (g=0)

    for (int g = tid; g < N_GRAINS; g += blockDim.x) {
        const int idx = b * N_GRAINS + g;
        const float u  = log2_f0_u[idx];
        const float f0 = exp2f(u * (LOG2_F0_MAX - LOG2_F0_MIN) + LOG2_F0_MIN);
        const float so = (1.0f - d) * (float)N_GRAINS * ((float)g / (float)N_GRAINS - offset);
        const float amp = 1.0f / (1.0f + expf(2.0f * so));
        g_coeff[idx] = (amp / amp0) / sqrtf(f0);
        g_f0s[idx]   = (double)f0 / SR;
    }

    if (b == 0) {
        for (int t = tid; t < GRAIN_N; t += blockDim.x) {
            const float w = sinpif((float)t / (float)GRAIN_N);
            g_window[t] = w * w;
        }
    }
}

// ============================================================
// Kernel 2: synth. grid (512, 32), 128 threads; one block per grain.
// Thread t owns contiguous samples [32t, 32t+32): fp64 seed once,
// then pure-fp32 phase walk with NO wrap (w stays bounded because
// every chunk reseeds; __sinf handles the range). Walk body is 4
// instructions: MUFU.SIN, STS, FADD, FMUL — no FSETP/BSSY.
// Staged via padded smem (conflict-free both directions), flushed
// with coalesced REDs. Window/coeff applied at flush.
// ============================================================
__global__ void __launch_bounds__(128)
synth_kernel(const int* __restrict__ onsets, float* __restrict__ out) {
    __shared__ float sbuf[32 * 129];   // sbuf[129*n + t] = sin for sample 32t+n

    const int g = blockIdx.x;
    const int b = blockIdx.y;
    const int idx = b * N_GRAINS + g;
    const int t   = threadIdx.x;

    const double f0s = g_f0s[idx];

    // fp64 seed for this chunk
    const double P0 = f0s * g_Sc[b * 128 + t];
    const double fr = P0 - rint(P0);                         // [-0.5, 0.5] cycles
    float w   = (float)(fr * TWO_PI_D);                      // radians
    float dlt = (float)(f0s * g_Dd[b * 128 + t] * TWO_PI_D); // rad/sample
    const float rho = g_rho[b];

    float* __restrict__ sp = &sbuf[t];
    #pragma unroll
    for (int n = 0; n < 32; n++) {
        sp[129 * n] = __sinf(w);   // no wrap: w bounded per chunk
        w += dlt;
        dlt *= rho;
    }
    __syncthreads();

    const int   onset = onsets[idx];
    const float coeff = g_coeff[idx];
    float* __restrict__ row = out + (size_t)b * N_SAMPLES + onset;
    const float* __restrict__ rp = &sbuf[129 * (t & 31) + (t >> 5)];

    #pragma unroll
    for (int i = 0; i < 32; i++) {
        const int s = 128 * i + t;                      // sample within grain
        atomicAdd(row + s, rp[4 * i] * coeff * g_window[s]);  // coalesced RED
    }
}

// ============================================================
// Kernel 3: norm^2. 2048 blocks (64/batch) x 256 threads, float4.
// ============================================================
__global__ void __launch_bounds__(256)
norm_kernel(const float4* __restrict__ out4) {
    const int b     = blockIdx.x >> 6;
    const int slice = blockIdx.x & 63;
    const int tid   = threadIdx.x;
    const float4* __restrict__ base = out4 + (size_t)b * 32768 + slice * 512;

    float s = 0.0f;
    #pragma unroll
    for (int k = 0; k < 2; k++) {
        const float4 v = base[tid + 256 * k];
        s += v.x * v.x + v.y * v.y + v.z * v.z + v.w * v.w;
    }
    __shared__ float sh[8];
    for (int off = 16; off > 0; off >>= 1)
        s += __shfl_down_sync(0xFFFFFFFFu, s, off);
    if ((tid & 31) == 0) sh[tid >> 5] = s;
    __syncthreads();
    if (tid < 8) {
        s = sh[tid];
        for (int off = 4; off > 0; off >>= 1)
            s += __shfl_down_sync(0xFFu, s, off);
        if (tid == 0) atomicAdd(&g_sum[b], (double)s);
    }
}

// ============================================================
// Kernel 4: scale by 1/norm. 1024 blocks x 256 threads, 4 float4 each.
// ============================================================
__global__ void __launch_bounds__(256)
scale_kernel(float4* __restrict__ out4) {
    const int b    = blockIdx.x >> 5;               // 32 blocks per batch
    const int base = blockIdx.x * 1024 + threadIdx.x;

    __shared__ float sinv;
    if (threadIdx.x == 0) sinv = (float)(1.0 / sqrt(g_sum[b]));
    __syncthreads();
    const float inv = sinv;

    #pragma unroll
    for (int k = 0; k < 4; k++) {
        float4 v = out4[base + 256 * k];
        v.x *= inv; v.y *= inv; v.z *= inv; v.w *= inv;
        out4[base + 256 * k] = v;
    }
}

extern "C" void kernel_launch(void* const* d_in, const int* in_sizes, int n_in,
                              void* d_out, int out_size) {
    const float* theta_d = (const float*)d_in[0];
    const float* theta_s = (const float*)d_in[1];
    const float* u       = (const float*)d_in[2];
    const int*   onsets  = (const int*)d_in[3];
    float* out = (float*)d_out;

    cudaMemsetAsync(out, 0, (size_t)BATCH * N_SAMPLES * sizeof(float));

    prep_kernel<<<BATCH, 512>>>(theta_d, theta_s, u);

    dim3 grid(N_GRAINS, BATCH);
    synth_kernel<<<grid, 128>>>(onsets, out);

    norm_kernel<<<2048, 256>>>((const float4*)out);

    scale_kernel<<<1024, 256>>>((float4*)out);
}

// round 10
// speedup vs baseline: 1.2771x; 1.2621x over previous
#include <cuda_runtime.h>
#include <math.h>

#define SR          44100.0
#define N_SAMPLES   131072
#define N_GRAINS    512
#define GRAIN_N     4096
#define BATCH       32
#define LOG2_F0_MIN 8.0f      /* log2(256) */
#define LOG2_F0_MAX 13.0f     /* log2(8192) */
#define TYP_SLOPE   14.35546875f  /* 44100/(12*256) */
#define PI_F        3.14159265358979323846f
#define TWO_PI_F    6.28318530717958647692f
#define TWO_PI_D    6.283185307179586476925286766559

// ---- scratch (no allocations allowed) ----
__device__ double g_S4[BATCH * 1024];        // S[4k] per batch
__device__ double g_D4[BATCH * 1024];        // D(4k) = S[4k+1]-S[4k]
__device__ double g_cj[BATCH * 4];           // (rho^j - 1)/(rho - 1), j=0..3
__device__ double g_rhoh[BATCH * 4];         // rho^j
__device__ double g_r512[BATCH];             // rho^512
__device__ double g_q512[BATCH];             // S[s+512] = r512*S[s] + q512
__device__ float  g_rhof[BATCH];             // (float)rho
__device__ float  g_r512f[BATCH];            // (float)rho^512
__device__ double g_f0s[BATCH * N_GRAINS];   // f0/SR per grain
__device__ float  g_coeff[BATCH * N_GRAINS]; // amp_norm / sqrt(f0)
__device__ float  g_window[GRAIN_N];         // sin^2(pi t / GRAIN_N)
__device__ float4 g_win4[4 * 1024];          // window shifted by h, packed 4-wide
__device__ double g_sum[BATCH];              // ||x||^2 accumulator

// ============================================================
// Kernel 1: prep. 32 blocks x 512 threads (block b = batch b).
//  Closed form of the reference cumsum (grain factored out):
//   S[s] = pref*expm1(a(s+1))/denom, a=gamma*ln2/SR, rho=e^a,
//   D(s) = S[s+1]-S[s] = pref*e^{a(s+1)},
//   S[s+j] = S[s] + D(s)*(rho^j-1)/(rho-1),
//   S[s+512] = rho^512 * S[s] + pref*(rho^512-1)/denom.
// ============================================================
__global__ void prep_kernel(const float* __restrict__ theta_d,
                            const float* __restrict__ theta_s,
                            const float* __restrict__ log2_f0_u) {
    const int b   = blockIdx.x;
    const int tid = threadIdx.x;

    const float d     = theta_d[b];
    const float slope = theta_s[b] * 2.0f - 1.0f;
    const float gamma_f = tanf(0.95f * slope * (PI_F * 0.5f)) * TYP_SLOPE * 0.25f;
    const double a = (double)gamma_f * 0.6931471805599453 / SR;

    if (a == 0.0) {
        for (int k = tid; k < 1024; k += 512) {
            g_S4[b * 1024 + k] = (double)(4 * k + 1);
            g_D4[b * 1024 + k] = 1.0;
        }
        if (tid == 0) {
            for (int j = 0; j < 4; j++) { g_cj[b*4+j] = (double)j; g_rhoh[b*4+j] = 1.0; }
            g_r512[b] = 1.0;  g_q512[b] = 512.0;
            g_rhof[b] = 1.0f; g_r512f[b] = 1.0f;
            g_sum[b]  = 0.0;
        }
    } else {
        const double pref  = exp(-2048.0 * a);
        const double denom = expm1(a);
        for (int k = tid; k < 1024; k += 512) {
            g_S4[b * 1024 + k] = pref * expm1(a * (double)(4 * k + 1)) / denom;
            g_D4[b * 1024 + k] = pref * exp(a * (double)(4 * k + 1));
        }
        if (tid == 0) {
            const double rho  = exp(a);
            const double r512 = exp(512.0 * a);
            double c = 0.0, rj = 1.0;
            for (int j = 0; j < 4; j++) {
                g_cj[b*4+j]   = c;
                g_rhoh[b*4+j] = rj;
                c += rj; rj *= rho;
            }
            g_r512[b] = r512;
            g_q512[b] = pref * (r512 - 1.0) / denom;
            g_rhof[b] = (float)rho;
            g_r512f[b] = (float)r512;
            g_sum[b]  = 0.0;
        }
    }

    // ---- per-grain quantities ----
    const float offset = 0.25f * d + 0.75f * d * d;
    const float so0  = (1.0f - d) * (float)N_GRAINS * (0.0f - offset);
    const float amp0 = 1.0f / (1.0f + expf(2.0f * so0));   // max amp (g=0)

    for (int g = tid; g < N_GRAINS; g += 512) {
        const int idx = b * N_GRAINS + g;
        const float u  = log2_f0_u[idx];
        const float f0 = exp2f(u * (LOG2_F0_MAX - LOG2_F0_MIN) + LOG2_F0_MIN);
        const float so = (1.0f - d) * (float)N_GRAINS * ((float)g / (float)N_GRAINS - offset);
        const float amp = 1.0f / (1.0f + expf(2.0f * so));
        g_coeff[idx] = (amp / amp0) / sqrtf(f0);
        g_f0s[idx]   = (double)f0 / SR;
    }

    // window tables (blocks 0-7: plain; blocks 8-11: shifted float4)
    if (b < 8) {
        const int t = b * 512 + tid;
        const float w = sinpif((float)t / (float)GRAIN_N);
        g_window[t] = w * w;
    } else if (b < 12) {
        const int h = b - 8;
        for (int k = tid; k < 1024; k += 512) {
            float4 wv;
            float* wp = (float*)&wv;
            #pragma unroll
            for (int j = 0; j < 4; j++) {
                const int s = h + 4 * k + j;
                if (s < GRAIN_N) {
                    const float w = sinpif((float)s / (float)GRAIN_N);
                    wp[j] = w * w;
                } else wp[j] = 0.0f;
            }
            g_win4[h * 1024 + k] = wv;
        }
    }
}

// ============================================================
// Kernel 2: synth. grid (512, 32), 128 threads; 1 block per grain.
// Thread t, iteration i handles 4 contiguous samples s=h+4(128i+t):
//  - 1 fp64 affine recurrence (stride 512) + 1 frac per 4 samples
//  - 3 fp32 phase steps inside the vector (re-seeded every 4)
//  - one red.global.add.v4.f32 per vector (16B-aligned via head
//    shift h), <=4 scalar edge atomics per grain.
// ============================================================
__global__ void __launch_bounds__(128)
synth_kernel(const int* __restrict__ onsets, float* __restrict__ out) {
    const int g = blockIdx.x;
    const int b = blockIdx.y;
    const int t = threadIdx.x;
    const int idx = b * N_GRAINS + g;

    const int onset = onsets[idx];
    const int h     = (4 - (onset & 3)) & 3;        // head shift for 16B alignment
    const int nvec  = (GRAIN_N - h) >> 2;           // 1024 (h=0) or 1023

    const double f0s   = g_f0s[idx];
    const float  coeff = g_coeff[idx];
    const double r512  = g_r512[b];
    const double fq512 = f0s * g_q512[b];
    const float  rhof  = g_rhof[b];
    const float  r512f = g_r512f[b];

    const double S4t = g_S4[b * 1024 + t];
    const double D4t = g_D4[b * 1024 + t];

    // phase (cycles) at sample s0 = h + 4t, and fp32 per-sample step (radians)
    double P   = f0s * (S4t + D4t * g_cj[b * 4 + h]);
    float  dlt = (float)(f0s * D4t * g_rhoh[b * 4 + h] * TWO_PI_D);

    float* __restrict__ row = out + (size_t)b * N_SAMPLES + onset + h;  // 16B aligned
    const float4* __restrict__ wrow = g_win4 + h * 1024;

    #pragma unroll
    for (int i = 0; i < 8; i++) {
        const int v = (i << 7) + t;                 // vector index
        const double fr = P - rint(P);              // [-0.5,0.5] cycles
        const float w0 = (float)fr * TWO_PI_F;
        const float w1 = w0 + dlt;
        const float d2 = dlt * rhof;
        const float w2 = w1 + d2;
        const float w3 = w2 + d2 * rhof;
        const float s0 = __sinf(w0), s1 = __sinf(w1);
        const float s2 = __sinf(w2), s3 = __sinf(w3);
        if (v < nvec) {
            const float4 wv = wrow[v];
            const float a0 = s0 * coeff * wv.x;
            const float a1 = s1 * coeff * wv.y;
            const float a2 = s2 * coeff * wv.z;
            const float a3 = s3 * coeff * wv.w;
            asm volatile("red.global.add.v4.f32 [%0], {%1, %2, %3, %4};"
                         :: "l"(row + 4 * v), "f"(a0), "f"(a1), "f"(a2), "f"(a3)
                         : "memory");
        }
        P = fma(r512, P, fq512);
        dlt *= r512f;
    }

    // edge samples (only when h>0): {0..h-1} and {4092+h..4095}
    if (h != 0 && t < 4) {
        const int e = (t < h) ? t : 4092 + t;
        const int k = e >> 2, j = e & 3;
        const double Pe  = f0s * (g_S4[b * 1024 + k] + g_D4[b * 1024 + k] * g_cj[b * 4 + j]);
        const double fre = Pe - rint(Pe);
        const float  we  = (float)fre * TWO_PI_F;
        const float  ve  = __sinf(we) * coeff * g_window[e];
        atomicAdd(out + (size_t)b * N_SAMPLES + onset + e, ve);
    }
}

// ============================================================
// Kernel 3: norm^2. 2048 blocks (64/batch) x 256 threads, float4.
// ============================================================
__global__ void __launch_bounds__(256)
norm_kernel(const float4* __restrict__ out4) {
    const int b     = blockIdx.x >> 6;
    const int slice = blockIdx.x & 63;
    const int tid   = threadIdx.x;
    const float4* __restrict__ base = out4 + (size_t)b * 32768 + slice * 512;

    float s = 0.0f;
    #pragma unroll
    for (int k = 0; k < 2; k++) {
        const float4 v = base[tid + 256 * k];
        s += v.x * v.x + v.y * v.y + v.z * v.z + v.w * v.w;
    }
    __shared__ float sh[8];
    for (int off = 16; off > 0; off >>= 1)
        s += __shfl_down_sync(0xFFFFFFFFu, s, off);
    if ((tid & 31) == 0) sh[tid >> 5] = s;
    __syncthreads();
    if (tid < 8) {
        s = sh[tid];
        for (int off = 4; off > 0; off >>= 1)
            s += __shfl_down_sync(0xFFu, s, off);
        if (tid == 0) atomicAdd(&g_sum[b], (double)s);
    }
}

// ============================================================
// Kernel 4: scale. 1024 blocks x 256 threads, 4 float4 each.
// Per-thread rsqrtf — no barrier, no fp64 sqrt dependency chain.
// ============================================================
__global__ void __launch_bounds__(256)
scale_kernel(float4* __restrict__ out4) {
    const int b    = blockIdx.x >> 5;               // 32 blocks per batch
    const int base = blockIdx.x * 1024 + threadIdx.x;

    const float inv = rsqrtf((float)g_sum[b]);

    #pragma unroll
    for (int k = 0; k < 4; k++) {
        float4 v = out4[base + 256 * k];
        v.x *= inv; v.y *= inv; v.z *= inv; v.w *= inv;
        out4[base + 256 * k] = v;
    }
}

extern "C" void kernel_launch(void* const* d_in, const int* in_sizes, int n_in,
                              void* d_out, int out_size) {
    const float* theta_d = (const float*)d_in[0];
    const float* theta_s = (const float*)d_in[1];
    const float* u       = (const float*)d_in[2];
    const int*   onsets  = (const int*)d_in[3];
    float* out = (float*)d_out;

    cudaMemsetAsync(out, 0, (size_t)BATCH * N_SAMPLES * sizeof(float));

    prep_kernel<<<BATCH, 512>>>(theta_d, theta_s, u);

    dim3 grid(N_GRAINS, BATCH);
    synth_kernel<<<grid, 128>>>(onsets, out);

    norm_kernel<<<2048, 256>>>((const float4*)out);

    scale_kernel<<<1024, 256>>>((float4*)out);
}